// round 1
// baseline (speedup 1.0000x reference)
#include <cuda_runtime.h>
#include <math.h>

// Problem dims
#define Bn   8
#define N1D  256
#define N2D  256
#define FD   128
#define ROWS (Bn * N1D)          // 2048

// ---------------- device scratch (no allocations allowed) ----------------
__device__ float g_Mx2[Bn * N2D * FD];       // M(x2)            [2048,128]
__device__ float g_m1 [ROWS * FD];           // W(x1)            [2048,128]
__device__ float g_gh [ROWS * 3 * FD];       // x1 @ whh^T + bhh [2048,384]
__device__ float g_x  [ROWS * FD];           // relu(m1+m2)      [2048,128]
__device__ float g_gi [ROWS * 3 * FD];       // x @ wih^T + bih  [2048,384]
__device__ int   g_cnt [ROWS];               // valid-edge counts
__device__ int   g_list[ROWS * N2D];         // valid-edge j lists

// ---------------- SGEMM tile: C[r,c] = sum_f A[r,f]*W[c,f] + bias[c] ------
// Block: 128 threads, tile 64 rows x 128 cols, K = 128 (full).
// Microtile 8x8 per thread. Smem rows padded to 132 floats (16B-aligned).
#define LDA 132
#define RT  64
#define CT  128
#define KD  128

__device__ __forceinline__ void gemm_tile(
    const float* __restrict__ A,      // [*, 128] row-major
    const float* __restrict__ Wseg,   // [>=128, 128] row-major (already col-offset)
    const float* __restrict__ bseg,   // [>=128]      (already col-offset)
    float* __restrict__ C, int ldC, int rowbase, int coutbase, float* sm)
{
    float* As = sm;                   // RT x LDA
    float* Ws = sm + RT * LDA;        // CT x LDA
    const int tid = threadIdx.x;

    // Stage A tile: 64x128 floats = 2048 float4, 16 per thread
#pragma unroll
    for (int it = 0; it < (RT * KD / 4) / 128; it++) {
        int idx = tid + it * 128;
        int r = idx >> 5, kf = idx & 31;
        float4 v = *(const float4*)(A + (size_t)(rowbase + r) * KD + kf * 4);
        *(float4*)(As + r * LDA + kf * 4) = v;
    }
    // Stage W tile: 128x128 floats = 4096 float4, 32 per thread
#pragma unroll
    for (int it = 0; it < (CT * KD / 4) / 128; it++) {
        int idx = tid + it * 128;
        int c = idx >> 5, kf = idx & 31;
        float4 v = *(const float4*)(Wseg + (size_t)c * KD + kf * 4);
        *(float4*)(Ws + c * LDA + kf * 4) = v;
    }
    __syncthreads();

    const int cg = tid & 15;          // 16 col-groups
    const int rg = tid >> 4;          // 8 row-groups

    float acc[8][8];
#pragma unroll
    for (int r = 0; r < 8; r++)
#pragma unroll
        for (int c = 0; c < 8; c++) acc[r][c] = 0.0f;

    const float* ap  = As + rg * 8 * LDA;
    const float* wp0 = Ws + (cg * 4) * LDA;
    const float* wp1 = Ws + (64 + cg * 4) * LDA;

#pragma unroll 2
    for (int kf = 0; kf < 32; kf++) {
        float4 a[8], w[8];
#pragma unroll
        for (int r = 0; r < 8; r++) a[r] = *(const float4*)(ap + r * LDA + kf * 4);
#pragma unroll
        for (int c = 0; c < 4; c++) w[c]     = *(const float4*)(wp0 + c * LDA + kf * 4);
#pragma unroll
        for (int c = 0; c < 4; c++) w[4 + c] = *(const float4*)(wp1 + c * LDA + kf * 4);
#pragma unroll
        for (int r = 0; r < 8; r++)
#pragma unroll
            for (int c = 0; c < 8; c++) {
                acc[r][c] += a[r].x * w[c].x;
                acc[r][c] += a[r].y * w[c].y;
                acc[r][c] += a[r].z * w[c].z;
                acc[r][c] += a[r].w * w[c].w;
            }
    }

    // Epilogue: add bias, store
#pragma unroll
    for (int c = 0; c < 8; c++) {
        int col = (c < 4) ? (cg * 4 + c) : (64 + cg * 4 + (c - 4));
        float bv = __ldg(bseg + col);
#pragma unroll
        for (int r = 0; r < 8; r++) {
            int row = rowbase + rg * 8 + r;
            C[(size_t)row * ldC + coutbase + col] = acc[r][c] + bv;
        }
    }
}

// Fused "input GEMMs" launch: y=0 -> Mx2, y=1 -> m1, y=2..4 -> gh chunks
__global__ void __launch_bounds__(128) k_gemmA(
    const float* __restrict__ x1, const float* __restrict__ x2,
    const float* __restrict__ W_w, const float* __restrict__ W_b,
    const float* __restrict__ M_w, const float* __restrict__ M_b,
    const float* __restrict__ whh, const float* __restrict__ bhh)
{
    extern __shared__ float sm[];
    int rowbase = blockIdx.x * RT;
    int y = blockIdx.y;
    if (y == 0) {
        gemm_tile(x2, M_w, M_b, g_Mx2, FD, rowbase, 0, sm);
    } else if (y == 1) {
        gemm_tile(x1, W_w, W_b, g_m1, FD, rowbase, 0, sm);
    } else {
        int cb = (y - 2) * 128;
        gemm_tile(x1, whh + (size_t)cb * KD, bhh + cb, g_gh, 3 * FD, rowbase, cb, sm);
    }
}

// gi = x @ wih^T + bih
__global__ void __launch_bounds__(128) k_gemmGI(
    const float* __restrict__ wih, const float* __restrict__ bih)
{
    extern __shared__ float sm[];
    int rowbase = blockIdx.x * RT;
    int cb = blockIdx.y * 128;
    gemm_tile(g_x, wih + (size_t)cb * KD, bih + cb, g_gi, 3 * FD, rowbase, cb, sm);
}

// ---------------- edge-list compaction (warp per row) ---------------------
__global__ void __launch_bounds__(256) k_lists(const float* __restrict__ ve)
{
    int w = threadIdx.x >> 5, lane = threadIdx.x & 31;
    int row = blockIdx.x * 8 + w;
    const float* mrow = ve + (size_t)row * N2D;
    int base = 0;
#pragma unroll
    for (int r = 0; r < 8; r++) {
        int j = r * 32 + lane;
        float v = mrow[j];
        unsigned bal = __ballot_sync(0xffffffffu, v != 0.0f);
        if (v != 0.0f)
            g_list[(size_t)row * N2D + base + __popc(bal & ((1u << lane) - 1u))] = j;
        base += __popc(bal);
    }
    if (lane == 0) g_cnt[row] = base;
}

// ---------------- sparse masked max + relu(m1 + m2) -----------------------
// 256 threads: g = tid&127 (feature), s = tid>>7 picks half of 8 rows/block.
__global__ void __launch_bounds__(256) k_maskmax()
{
    int g = threadIdx.x & 127;
    int s = threadIdx.x >> 7;
    int rowbase = blockIdx.x * 8 + s * 4;
#pragma unroll
    for (int ii = 0; ii < 4; ii++) {
        int row = rowbase + ii;
        int b = row >> 8;
        const float* __restrict__ Mb = g_Mx2 + (size_t)b * N2D * FD;
        const int*   __restrict__ lst = g_list + (size_t)row * N2D;
        int cnt = g_cnt[row];
        float m = -3.402823466e38f;
        int t = 0;
        for (; t + 4 <= cnt; t += 4) {
            int j0 = __ldg(lst + t),     j1 = __ldg(lst + t + 1);
            int j2 = __ldg(lst + t + 2), j3 = __ldg(lst + t + 3);
            float v0 = Mb[j0 * FD + g], v1 = Mb[j1 * FD + g];
            float v2 = Mb[j2 * FD + g], v3 = Mb[j3 * FD + g];
            m = fmaxf(m, fmaxf(fmaxf(v0, v1), fmaxf(v2, v3)));
        }
        for (; t < cnt; t++) m = fmaxf(m, Mb[__ldg(lst + t) * FD + g]);
        if (cnt < N2D) m = fmaxf(m, 0.0f);   // missing edges contribute exact 0
        float xv = g_m1[(size_t)row * FD + g] + m;
        g_x[(size_t)row * FD + g] = fmaxf(xv, 0.0f);
    }
}

// ---------------- GRU gates -----------------------------------------------
__global__ void __launch_bounds__(256) k_gates(
    const float* __restrict__ x1, float* __restrict__ out)
{
    int idx = blockIdx.x * 256 + threadIdx.x;
    int row = idx >> 7, f = idx & 127;
    const float* gi = g_gi + (size_t)row * 384;
    const float* gh = g_gh + (size_t)row * 384;
    float r = 1.0f / (1.0f + expf(-(gi[f]       + gh[f])));
    float z = 1.0f / (1.0f + expf(-(gi[128 + f] + gh[128 + f])));
    float n = tanhf(gi[256 + f] + r * gh[256 + f]);
    float hp = x1[idx];
    out[idx] = (1.0f - z) * n + z * hp;
}

// ---------------- launch ---------------------------------------------------
extern "C" void kernel_launch(void* const* d_in, const int* in_sizes, int n_in,
                              void* d_out, int out_size)
{
    const float* x1  = (const float*)d_in[0];
    const float* x2  = (const float*)d_in[1];
    const float* ve  = (const float*)d_in[2];
    const float* W_w = (const float*)d_in[3];
    const float* W_b = (const float*)d_in[4];
    const float* M_w = (const float*)d_in[5];
    const float* M_b = (const float*)d_in[6];
    const float* wih = (const float*)d_in[7];
    const float* whh = (const float*)d_in[8];
    const float* bih = (const float*)d_in[9];
    const float* bhh = (const float*)d_in[10];
    float* out = (float*)d_out;

    const int smem = (RT + CT) * LDA * (int)sizeof(float);   // 101376 B
    cudaFuncSetAttribute(k_gemmA,  cudaFuncAttributeMaxDynamicSharedMemorySize, smem);
    cudaFuncSetAttribute(k_gemmGI, cudaFuncAttributeMaxDynamicSharedMemorySize, smem);

    k_lists<<<ROWS / 8, 256>>>(ve);
    k_gemmA<<<dim3(ROWS / RT, 5), 128, smem>>>(x1, x2, W_w, W_b, M_w, M_b, whh, bhh);
    k_maskmax<<<ROWS / 8, 256>>>();
    k_gemmGI<<<dim3(ROWS / RT, 3), 128, smem>>>(wih, bih);
    k_gates<<<(ROWS * FD) / 256, 256>>>(x1, out);
}

// round 2
// speedup vs baseline: 1.1654x; 1.1654x over previous
#include <cuda_runtime.h>
#include <math.h>
#include <float.h>

// Problem dims
#define Bn   8
#define N1D  256
#define N2D  256
#define FD   128
#define ROWS (Bn * N1D)          // 2048
#define KD   128

// GEMM tiling: 64x64 tile per 256-thread CTA, 4x4 microtile.
#define RT  64
#define CT  64
#define LDT 68                   // padded minor dim of [k][*] smem tiles

// ---------------- device scratch (no allocations allowed) ----------------
__device__ float g_Mx2[Bn * N2D * FD];       // M(x2)            [2048,128]
__device__ float g_m1 [ROWS * FD];           // W(x1)            [2048,128]
__device__ float g_gh [ROWS * 3 * FD];       // x1 @ whh^T + bhh [2048,384]
__device__ float g_x  [ROWS * FD];           // relu(m1+m2)      [2048,128]
__device__ float g_gi [ROWS * 3 * FD];       // x @ wih^T + bih  [2048,384]
__device__ int   g_cnt [ROWS];               // valid-edge counts
__device__ int   g_list[ROWS * N2D];         // valid-edge j lists

// ---------------- SGEMM tile: C[r,c] = sum_f A[r,f]*W[c,f] + bias[c] ------
// Smem tiles are stored K-major ([k][r] / [k][c]) so the inner loop does
// conflict-free LDS.128 (a: 2-addr broadcast; w: 16 consecutive float4).
__device__ __forceinline__ void gemm_tile(
    const float* __restrict__ A,      // [*, 128] row-major
    const float* __restrict__ W,      // [>=colbase+64, 128] row-major
    const float* __restrict__ b,      // [>=colbase+64]
    float* __restrict__ C, int ldC, int rowbase, int colbase, float* sm)
{
    float* As = sm;                   // [KD][LDT]
    float* Ws = sm + KD * LDT;        // [KD][LDT]
    const int tid  = threadIdx.x;
    const int lane = tid & 31, warp = tid >> 5;
    const int kq = lane & 3;          // which float4 along k
    const int rr = lane >> 2;         // 0..7
    const int r  = warp * 8 + rr;     // 0..63 (row / col within tile)

    // Stage with transpose: global row-major -> smem K-major.
#pragma unroll
    for (int it = 0; it < 8; it++) {
        int kk = it * 4 + kq;         // k/4 index, 0..31
        float4 av = *(const float4*)(A + (size_t)(rowbase + r) * KD + kk * 4);
        As[(kk * 4 + 0) * LDT + r] = av.x;
        As[(kk * 4 + 1) * LDT + r] = av.y;
        As[(kk * 4 + 2) * LDT + r] = av.z;
        As[(kk * 4 + 3) * LDT + r] = av.w;
        float4 wv = *(const float4*)(W + (size_t)(colbase + r) * KD + kk * 4);
        Ws[(kk * 4 + 0) * LDT + r] = wv.x;
        Ws[(kk * 4 + 1) * LDT + r] = wv.y;
        Ws[(kk * 4 + 2) * LDT + r] = wv.z;
        Ws[(kk * 4 + 3) * LDT + r] = wv.w;
    }
    __syncthreads();

    const int cg = tid & 15;          // col group (4 cols)
    const int rg = tid >> 4;          // row group (4 rows)

    float acc[4][4];
#pragma unroll
    for (int i = 0; i < 4; i++)
#pragma unroll
        for (int j = 0; j < 4; j++) acc[i][j] = 0.0f;

    const float* ap = As + rg * 4;
    const float* wp = Ws + cg * 4;

#pragma unroll 8
    for (int k = 0; k < KD; k++) {
        float4 a = *(const float4*)(ap + k * LDT);
        float4 w = *(const float4*)(wp + k * LDT);
        acc[0][0] += a.x * w.x; acc[0][1] += a.x * w.y; acc[0][2] += a.x * w.z; acc[0][3] += a.x * w.w;
        acc[1][0] += a.y * w.x; acc[1][1] += a.y * w.y; acc[1][2] += a.y * w.z; acc[1][3] += a.y * w.w;
        acc[2][0] += a.z * w.x; acc[2][1] += a.z * w.y; acc[2][2] += a.z * w.z; acc[2][3] += a.z * w.w;
        acc[3][0] += a.w * w.x; acc[3][1] += a.w * w.y; acc[3][2] += a.w * w.z; acc[3][3] += a.w * w.w;
    }

    float4 bv = *(const float4*)(b + colbase + cg * 4);
#pragma unroll
    for (int i = 0; i < 4; i++) {
        float4 o;
        o.x = acc[i][0] + bv.x;
        o.y = acc[i][1] + bv.y;
        o.z = acc[i][2] + bv.z;
        o.w = acc[i][3] + bv.w;
        *(float4*)(C + (size_t)(rowbase + rg * 4 + i) * ldC + colbase + cg * 4) = o;
    }
}

// Phase A: y 0-1 -> Mx2, y 2-3 -> m1, y 4-9 -> gh (384 cols)
__global__ void __launch_bounds__(256, 2) k_gemmA(
    const float* __restrict__ x1, const float* __restrict__ x2,
    const float* __restrict__ W_w, const float* __restrict__ W_b,
    const float* __restrict__ M_w, const float* __restrict__ M_b,
    const float* __restrict__ whh, const float* __restrict__ bhh)
{
    extern __shared__ float sm[];
    int rowbase = blockIdx.x * RT;
    int y = blockIdx.y;
    if (y < 2)
        gemm_tile(x2, M_w, M_b, g_Mx2, FD, rowbase, y * CT, sm);
    else if (y < 4)
        gemm_tile(x1, W_w, W_b, g_m1, FD, rowbase, (y - 2) * CT, sm);
    else
        gemm_tile(x1, whh, bhh, g_gh, 3 * FD, rowbase, (y - 4) * CT, sm);
}

// gi = x @ wih^T + bih
__global__ void __launch_bounds__(256, 2) k_gemmGI(
    const float* __restrict__ wih, const float* __restrict__ bih)
{
    extern __shared__ float sm[];
    gemm_tile(g_x, wih, bih, g_gi, 3 * FD, blockIdx.x * RT, blockIdx.y * CT, sm);
}

// ---------------- edge-list compaction (warp per row) ---------------------
__global__ void __launch_bounds__(256) k_lists(const float* __restrict__ ve)
{
    int w = threadIdx.x >> 5, lane = threadIdx.x & 31;
    int row = blockIdx.x * 8 + w;
    const float* mrow = ve + (size_t)row * N2D;
    int base = 0;
#pragma unroll
    for (int r = 0; r < 8; r++) {
        int j = r * 32 + lane;
        float v = mrow[j];
        unsigned bal = __ballot_sync(0xffffffffu, v != 0.0f);
        if (v != 0.0f)
            g_list[(size_t)row * N2D + base + __popc(bal & ((1u << lane) - 1u))] = j;
        base += __popc(bal);
    }
    if (lane == 0) g_cnt[row] = base;
}

// ---------------- sparse masked max + relu(m1 + m2) -----------------------
// Warp per row; each lane owns 4 features (float4).
__device__ __forceinline__ float4 max4(float4 a, float4 b) {
    float4 r;
    r.x = fmaxf(a.x, b.x); r.y = fmaxf(a.y, b.y);
    r.z = fmaxf(a.z, b.z); r.w = fmaxf(a.w, b.w);
    return r;
}

__global__ void __launch_bounds__(256) k_maskmax()
{
    int warp = threadIdx.x >> 5, lane = threadIdx.x & 31;
    int row = blockIdx.x * 8 + warp;
    int b = row >> 8;
    const float4* __restrict__ Mb = (const float4*)(g_Mx2 + (size_t)b * N2D * FD);
    const int* __restrict__ lst = g_list + (size_t)row * N2D;
    int cnt = g_cnt[row];

    float4 m = make_float4(-FLT_MAX, -FLT_MAX, -FLT_MAX, -FLT_MAX);
    int t = 0;
    for (; t + 4 <= cnt; t += 4) {
        int j0 = __ldg(lst + t),     j1 = __ldg(lst + t + 1);
        int j2 = __ldg(lst + t + 2), j3 = __ldg(lst + t + 3);
        float4 v0 = Mb[j0 * 32 + lane];
        float4 v1 = Mb[j1 * 32 + lane];
        float4 v2 = Mb[j2 * 32 + lane];
        float4 v3 = Mb[j3 * 32 + lane];
        m = max4(m, max4(max4(v0, v1), max4(v2, v3)));
    }
    for (; t < cnt; t++)
        m = max4(m, Mb[__ldg(lst + t) * 32 + lane]);
    if (cnt < N2D) {  // masked-out entries contribute exact 0
        float4 z = make_float4(0.f, 0.f, 0.f, 0.f);
        m = max4(m, z);
    }
    float4 m1v = ((const float4*)g_m1)[row * 32 + lane];
    float4 x;
    x.x = fmaxf(m1v.x + m.x, 0.f);
    x.y = fmaxf(m1v.y + m.y, 0.f);
    x.z = fmaxf(m1v.z + m.z, 0.f);
    x.w = fmaxf(m1v.w + m.w, 0.f);
    ((float4*)g_x)[row * 32 + lane] = x;
}

// ---------------- GRU gates -----------------------------------------------
__global__ void __launch_bounds__(256) k_gates(
    const float* __restrict__ x1, float* __restrict__ out)
{
    int idx = blockIdx.x * 256 + threadIdx.x;
    int row = idx >> 7, f = idx & 127;
    const float* gi = g_gi + (size_t)row * 384;
    const float* gh = g_gh + (size_t)row * 384;
    float r = 1.0f / (1.0f + expf(-(gi[f]       + gh[f])));
    float z = 1.0f / (1.0f + expf(-(gi[128 + f] + gh[128 + f])));
    float n = tanhf(gi[256 + f] + r * gh[256 + f]);
    float hp = x1[idx];
    out[idx] = (1.0f - z) * n + z * hp;
}

// ---------------- launch ---------------------------------------------------
extern "C" void kernel_launch(void* const* d_in, const int* in_sizes, int n_in,
                              void* d_out, int out_size)
{
    const float* x1  = (const float*)d_in[0];
    const float* x2  = (const float*)d_in[1];
    const float* ve  = (const float*)d_in[2];
    const float* W_w = (const float*)d_in[3];
    const float* W_b = (const float*)d_in[4];
    const float* M_w = (const float*)d_in[5];
    const float* M_b = (const float*)d_in[6];
    const float* wih = (const float*)d_in[7];
    const float* whh = (const float*)d_in[8];
    const float* bih = (const float*)d_in[9];
    const float* bhh = (const float*)d_in[10];
    float* out = (float*)d_out;

    const int smem = 2 * KD * LDT * (int)sizeof(float);   // 69632 B
    cudaFuncSetAttribute(k_gemmA,  cudaFuncAttributeMaxDynamicSharedMemorySize, smem);
    cudaFuncSetAttribute(k_gemmGI, cudaFuncAttributeMaxDynamicSharedMemorySize, smem);

    k_lists<<<ROWS / 8, 256>>>(ve);
    k_gemmA<<<dim3(ROWS / RT, 10), 256, smem>>>(x1, x2, W_w, W_b, M_w, M_b, whh, bhh);
    k_maskmax<<<ROWS / 8, 256>>>();
    k_gemmGI<<<dim3(ROWS / RT, 6), 256, smem>>>(wih, bih);
    k_gates<<<(ROWS * FD) / 256, 256>>>(x1, out);
}

// round 4
// speedup vs baseline: 1.8333x; 1.5732x over previous
#include <cuda_runtime.h>
#include <math.h>
#include <float.h>

// Problem dims
#define Bn   8
#define N1D  256
#define N2D  256
#define FD   128
#define ROWS (Bn * N1D)          // 2048
#define KD   128

// GEMM tiling: 64x64 tile per 256-thread CTA, 4x4 microtile.
#define RT  64
#define CT  64
#define LDT 68                   // padded minor dim of [k][*] smem tiles

// ---------------- device scratch (no allocations allowed) ----------------
__device__ float g_Mx2[Bn * N2D * FD];       // M(x2)            [2048,128]
__device__ float g_m1 [ROWS * FD];           // W(x1)            [2048,128]
__device__ float g_gh [ROWS * 3 * FD];       // x1 @ whh^T + bhh [2048,384]
__device__ float g_x  [ROWS * FD];           // relu(m1+m2)      [2048,128]
__device__ float g_gi [ROWS * 3 * FD];       // x @ wih^T + bih  [2048,384]
__device__ int   g_cnt [ROWS];               // valid-edge counts
__device__ int   g_list[ROWS * N2D];         // valid-edge j lists

// ---------------- SGEMM tile: C[r,c] = sum_f A[r,f]*W[c,f] + bias[c] ------
// Smem tiles are stored K-major ([k][r] / [k][c]) so the inner loop does
// conflict-free LDS.128 (a: 2-addr broadcast; w: 16 consecutive float4).
__device__ __forceinline__ void gemm_tile(
    const float* __restrict__ A,      // [*, 128] row-major
    const float* __restrict__ W,      // [>=colbase+64, 128] row-major
    const float* __restrict__ b,      // [>=colbase+64]
    float* __restrict__ C, int ldC, int rowbase, int colbase, float* sm)
{
    float* As = sm;                   // [KD][LDT]
    float* Ws = sm + KD * LDT;        // [KD][LDT]
    const int tid  = threadIdx.x;
    const int lane = tid & 31, warp = tid >> 5;
    const int kq = lane & 3;          // which float4 along k
    const int rr = lane >> 2;         // 0..7
    const int r  = warp * 8 + rr;     // 0..63 (row / col within tile)

    // Stage with transpose: global row-major -> smem K-major.
#pragma unroll
    for (int it = 0; it < 8; it++) {
        int kk = it * 4 + kq;         // k/4 index, 0..31
        float4 av = *(const float4*)(A + (size_t)(rowbase + r) * KD + kk * 4);
        As[(kk * 4 + 0) * LDT + r] = av.x;
        As[(kk * 4 + 1) * LDT + r] = av.y;
        As[(kk * 4 + 2) * LDT + r] = av.z;
        As[(kk * 4 + 3) * LDT + r] = av.w;
        float4 wv = *(const float4*)(W + (size_t)(colbase + r) * KD + kk * 4);
        Ws[(kk * 4 + 0) * LDT + r] = wv.x;
        Ws[(kk * 4 + 1) * LDT + r] = wv.y;
        Ws[(kk * 4 + 2) * LDT + r] = wv.z;
        Ws[(kk * 4 + 3) * LDT + r] = wv.w;
    }
    __syncthreads();

    const int cg = tid & 15;          // col group (4 cols)
    const int rg = tid >> 4;          // row group (4 rows)

    float acc[4][4];
#pragma unroll
    for (int i = 0; i < 4; i++)
#pragma unroll
        for (int j = 0; j < 4; j++) acc[i][j] = 0.0f;

    const float* ap = As + rg * 4;
    const float* wp = Ws + cg * 4;

#pragma unroll 8
    for (int k = 0; k < KD; k++) {
        float4 a = *(const float4*)(ap + k * LDT);
        float4 w = *(const float4*)(wp + k * LDT);
        acc[0][0] += a.x * w.x; acc[0][1] += a.x * w.y; acc[0][2] += a.x * w.z; acc[0][3] += a.x * w.w;
        acc[1][0] += a.y * w.x; acc[1][1] += a.y * w.y; acc[1][2] += a.y * w.z; acc[1][3] += a.y * w.w;
        acc[2][0] += a.z * w.x; acc[2][1] += a.z * w.y; acc[2][2] += a.z * w.z; acc[2][3] += a.z * w.w;
        acc[3][0] += a.w * w.x; acc[3][1] += a.w * w.y; acc[3][2] += a.w * w.z; acc[3][3] += a.w * w.w;
    }

    float4 bv = *(const float4*)(b + colbase + cg * 4);
#pragma unroll
    for (int i = 0; i < 4; i++) {
        float4 o;
        o.x = acc[i][0] + bv.x;
        o.y = acc[i][1] + bv.y;
        o.z = acc[i][2] + bv.z;
        o.w = acc[i][3] + bv.w;
        *(float4*)(C + (size_t)(rowbase + rg * 4 + i) * ldC + colbase + cg * 4) = o;
    }
}

// Edge-list compaction for 8 rows (one warp per row), given first row.
__device__ __forceinline__ void lists_block(const float* __restrict__ ve, int rowblock)
{
    int w = threadIdx.x >> 5, lane = threadIdx.x & 31;
    int row = rowblock * 8 + w;
    const float* mrow = ve + (size_t)row * N2D;
    int base = 0;
#pragma unroll
    for (int r = 0; r < 8; r++) {
        int j = r * 32 + lane;
        float v = mrow[j];
        unsigned bal = __ballot_sync(0xffffffffu, v != 0.0f);
        if (v != 0.0f)
            g_list[(size_t)row * N2D + base + __popc(bal & ((1u << lane) - 1u))] = j;
        base += __popc(bal);
    }
    if (lane == 0) g_cnt[row] = base;
}

// Phase 1 (flattened 1D grid, 576 blocks):
//   bid [0,64)    -> Mx2   (x 32 rowblocks, y 2 colblocks)
//   bid [64,128)  -> m1
//   bid [128,320) -> gh (6 colblocks)
//   bid [320,576) -> edge-list compaction (256 blocks, 8 rows each)
__global__ void __launch_bounds__(256, 3) k_p1(
    const float* __restrict__ x1, const float* __restrict__ x2,
    const float* __restrict__ ve,
    const float* __restrict__ W_w, const float* __restrict__ W_b,
    const float* __restrict__ M_w, const float* __restrict__ M_b,
    const float* __restrict__ whh, const float* __restrict__ bhh)
{
    extern __shared__ float sm[];
    int bid = blockIdx.x;
    if (bid < 64) {
        gemm_tile(x2, M_w, M_b, g_Mx2, FD, (bid & 31) * RT, (bid >> 5) * CT, sm);
    } else if (bid < 128) {
        int t = bid - 64;
        gemm_tile(x1, W_w, W_b, g_m1, FD, (t & 31) * RT, (t >> 5) * CT, sm);
    } else if (bid < 320) {
        int t = bid - 128;
        gemm_tile(x1, whh, bhh, g_gh, 3 * FD, (t & 31) * RT, (t >> 5) * CT, sm);
    } else {
        lists_block(ve, bid - 320);
    }
}

// gi = x @ wih^T + bih
__global__ void __launch_bounds__(256, 3) k_gemmGI(
    const float* __restrict__ wih, const float* __restrict__ bih)
{
    extern __shared__ float sm[];
    gemm_tile(g_x, wih, bih, g_gi, 3 * FD, blockIdx.x * RT, blockIdx.y * CT, sm);
}

// ---------------- sparse masked max + relu(m1 + m2) -----------------------
__device__ __forceinline__ float4 max4(float4 a, float4 b) {
    float4 r;
    r.x = fmaxf(a.x, b.x); r.y = fmaxf(a.y, b.y);
    r.z = fmaxf(a.z, b.z); r.w = fmaxf(a.w, b.w);
    return r;
}

__global__ void __launch_bounds__(256) k_maskmax()
{
    int warp = threadIdx.x >> 5, lane = threadIdx.x & 31;
    int row = blockIdx.x * 8 + warp;
    int b = row >> 8;
    const float4* __restrict__ Mb = (const float4*)(g_Mx2 + (size_t)b * N2D * FD);
    const int* __restrict__ lst = g_list + (size_t)row * N2D;
    int cnt = g_cnt[row];

    float4 m = make_float4(-FLT_MAX, -FLT_MAX, -FLT_MAX, -FLT_MAX);
    int t = 0;
    for (; t + 4 <= cnt; t += 4) {
        int j0 = __ldg(lst + t),     j1 = __ldg(lst + t + 1);
        int j2 = __ldg(lst + t + 2), j3 = __ldg(lst + t + 3);
        float4 v0 = Mb[j0 * 32 + lane];
        float4 v1 = Mb[j1 * 32 + lane];
        float4 v2 = Mb[j2 * 32 + lane];
        float4 v3 = Mb[j3 * 32 + lane];
        m = max4(m, max4(max4(v0, v1), max4(v2, v3)));
    }
    for (; t < cnt; t++)
        m = max4(m, Mb[__ldg(lst + t) * 32 + lane]);
    if (cnt < N2D) {  // masked-out entries contribute exact 0
        float4 z = make_float4(0.f, 0.f, 0.f, 0.f);
        m = max4(m, z);
    }
    float4 m1v = ((const float4*)g_m1)[row * 32 + lane];
    float4 x;
    x.x = fmaxf(m1v.x + m.x, 0.f);
    x.y = fmaxf(m1v.y + m.y, 0.f);
    x.z = fmaxf(m1v.z + m.z, 0.f);
    x.w = fmaxf(m1v.w + m.w, 0.f);
    ((float4*)g_x)[row * 32 + lane] = x;
}

// ---------------- GRU gates -----------------------------------------------
__global__ void __launch_bounds__(256) k_gates(
    const float* __restrict__ x1, float* __restrict__ out)
{
    int idx = blockIdx.x * 256 + threadIdx.x;
    int row = idx >> 7, f = idx & 127;
    const float* gi = g_gi + (size_t)row * 384;
    const float* gh = g_gh + (size_t)row * 384;
    float r = 1.0f / (1.0f + expf(-(gi[f]       + gh[f])));
    float z = 1.0f / (1.0f + expf(-(gi[128 + f] + gh[128 + f])));
    float n = tanhf(gi[256 + f] + r * gh[256 + f]);
    float hp = x1[idx];
    out[idx] = (1.0f - z) * n + z * hp;
}

// ---------------- launch ---------------------------------------------------
extern "C" void kernel_launch(void* const* d_in, const int* in_sizes, int n_in,
                              void* d_out, int out_size)
{
    const float* x1  = (const float*)d_in[0];
    const float* x2  = (const float*)d_in[1];
    const float* ve  = (const float*)d_in[2];
    const float* W_w = (const float*)d_in[3];
    const float* W_b = (const float*)d_in[4];
    const float* M_w = (const float*)d_in[5];
    const float* M_b = (const float*)d_in[6];
    const float* wih = (const float*)d_in[7];
    const float* whh = (const float*)d_in[8];
    const float* bih = (const float*)d_in[9];
    const float* bhh = (const float*)d_in[10];
    float* out = (float*)d_out;

    const int smem = 2 * KD * LDT * (int)sizeof(float);   // 69632 B
    cudaFuncSetAttribute(k_p1,     cudaFuncAttributeMaxDynamicSharedMemorySize, smem);
    cudaFuncSetAttribute(k_gemmGI, cudaFuncAttributeMaxDynamicSharedMemorySize, smem);

    k_p1<<<576, 256, smem>>>(x1, x2, ve, W_w, W_b, M_w, M_b, whh, bhh);
    k_maskmax<<<ROWS / 8, 256>>>();
    k_gemmGI<<<dim3(ROWS / RT, 6), 256, smem>>>(wih, bih);
    k_gates<<<(ROWS * FD) / 256, 256>>>(x1, out);
}